// round 16
// baseline (speedup 1.0000x reference)
#include <cuda_runtime.h>
#include <mma.h>
#include <math.h>
#include <stdint.h>
#include <cuda_fp16.h>

using namespace nvcuda;

#define GRIDN 16
#define NN 256
#define DD 64
#define BB 4096
#define FF 512
#define HH 16384
#define CC 1000
#define CPAD 1024

// ---------------- scratch ----------------------------------------------------
__device__ __half g_xh[(size_t)BB * FF];        // x rounded to fp16
__device__ __half g_win2h[(size_t)HH * FF];     // adj-folded W_in (fp16)
__device__ float  g_bin2[HH];                   // folded b_in (fp32)
__device__ __half g_wh[(size_t)BB * CPAD];      // softmax weights (fp16)
__device__ __half g_mmath[(size_t)CC * CPAD];   // folded basis x W_out (fp16)
__device__ float  g_adjw[NN * 4];
__device__ int    g_adjn[NN * 4];
__device__ float  g_K[4 * DD];

__device__ __forceinline__ float sigmoidf_(float x) { return 1.0f / (1.0f + expf(-x)); }
__device__ __forceinline__ float clip3(float x) { return fminf(fmaxf(x, -3.0f), 3.0f); }

// ---------------- prep: adjacency rows + K = basis @ k_w^T + k_b ------------
__global__ void prep_kernel(const float* __restrict__ adjw,
                            const float* __restrict__ k_w,
                            const float* __restrict__ k_b,
                            const float* __restrict__ basis)
{
    int t = threadIdx.x;
    int r = t >> 4, c = t & 15;
    int nb[4]; int cnt = 0;
    if (r > 0)         nb[cnt++] = t - GRIDN;
    if (r < GRIDN - 1) nb[cnt++] = t + GRIDN;
    if (c > 0)         nb[cnt++] = t - 1;
    if (c < GRIDN - 1) nb[cnt++] = t + 1;

    float w[4] = {0.f, 0.f, 0.f, 0.f};
    float deg = 0.f;
    for (int j = 0; j < cnt; j++) { w[j] = sigmoidf_(adjw[t * NN + nb[j]]); deg += w[j]; }
    deg = fmaxf(deg, 1e-6f);
    int over = 0;
    for (int j = 0; j < cnt; j++) { w[j] /= deg; if (w[j] > 0.1f) over++; }
    if (over < 1) w[0] = fmaxf(w[0], 0.5f);
    for (int j = 0; j < 4; j++) {
        g_adjw[t * 4 + j] = (j < cnt) ? w[j] : 0.f;
        g_adjn[t * 4 + j] = (j < cnt) ? nb[j] : t;
    }

    int kr = t >> 6, kc = t & 63;
    float acc = k_b[kc];
    for (int d = 0; d < DD; d++) acc += basis[kr * DD + d] * k_w[kc * DD + d];
    g_K[kr * DD + kc] = acc;
}

// ---------------- combined prep2: fold_win | round_x | mmat ------------------
#define FOLD_BLKS  (HH * (FF / 4) / 256)        // 8192
#define RX_BLKS    (BB * (FF / 4) / 256)        // 2048
#define MMAT_BLKS  ((CC * NN) / 4 / 8)          // 8000
#define PREP2_GRID (FOLD_BLKS + RX_BLKS + MMAT_BLKS)

__global__ void prep2_kernel(const float* __restrict__ W_in, const float* __restrict__ b_in,
                             const float* __restrict__ x,
                             const float* __restrict__ W_out, const float* __restrict__ basis)
{
    int blk = blockIdx.x;
    int t = threadIdx.x;

    if (blk < FOLD_BLKS) {
        int idx = blk * 256 + t;
        int row = idx >> 7, c4 = idx & 127;
        int n = row >> 6, d = row & 63;
        float w0 = g_adjw[n * 4 + 0], w1 = g_adjw[n * 4 + 1];
        float w2 = g_adjw[n * 4 + 2], w3 = g_adjw[n * 4 + 3];
        int   r0 = g_adjn[n * 4 + 0] * DD + d, r1 = g_adjn[n * 4 + 1] * DD + d;
        int   r2 = g_adjn[n * 4 + 2] * DD + d, r3 = g_adjn[n * 4 + 3] * DD + d;
        float4 a = ((const float4*)(W_in + (size_t)r0 * FF))[c4];
        float4 b = ((const float4*)(W_in + (size_t)r1 * FF))[c4];
        float4 c = ((const float4*)(W_in + (size_t)r2 * FF))[c4];
        float4 e = ((const float4*)(W_in + (size_t)r3 * FF))[c4];
        __half2 h0 = __floats2half2_rn(w0 * a.x + w1 * b.x + w2 * c.x + w3 * e.x,
                                       w0 * a.y + w1 * b.y + w2 * c.y + w3 * e.y);
        __half2 h1 = __floats2half2_rn(w0 * a.z + w1 * b.z + w2 * c.z + w3 * e.z,
                                       w0 * a.w + w1 * b.w + w2 * c.w + w3 * e.w);
        __half2* dst = (__half2*)(g_win2h + (size_t)row * FF + c4 * 4);
        dst[0] = h0; dst[1] = h1;
        if (c4 == 0)
            g_bin2[row] = w0 * b_in[r0] + w1 * b_in[r1] + w2 * b_in[r2] + w3 * b_in[r3];
    } else if (blk < FOLD_BLKS + RX_BLKS) {
        int i = (blk - FOLD_BLKS) * 256 + t;
        float4 v = ((const float4*)x)[i];
        __half2* dst = (__half2*)(g_xh + (size_t)i * 4);
        dst[0] = __floats2half2_rn(v.x, v.y);
        dst[1] = __floats2half2_rn(v.z, v.w);
    } else {
        int gw = ((blk - FOLD_BLKS - RX_BLKS) * 256 + t) >> 5;
        int lane = t & 31;
        int rowi = gw * 4;
        if (rowi >= CC * NN) return;
        const float* rp = W_out + (size_t)rowi * DD;
        float a0 = rp[lane],            a1 = rp[lane + 32];
        float b0 = rp[64 + lane],       b1 = rp[96 + lane];
        float c0 = rp[128 + lane],      c1 = rp[160 + lane];
        float d0 = rp[192 + lane],      d1 = rp[224 + lane];
        float ba0 = basis[lane],        ba1 = basis[lane + 32];
        float bb0 = basis[64 + lane],   bb1 = basis[96 + lane];
        float bc0 = basis[128 + lane],  bc1 = basis[160 + lane];
        float bd0 = basis[192 + lane],  bd1 = basis[224 + lane];
        float r[16];
        r[0]  = a0 * ba0 + a1 * ba1;  r[1]  = a0 * bb0 + a1 * bb1;
        r[2]  = a0 * bc0 + a1 * bc1;  r[3]  = a0 * bd0 + a1 * bd1;
        r[4]  = b0 * ba0 + b1 * ba1;  r[5]  = b0 * bb0 + b1 * bb1;
        r[6]  = b0 * bc0 + b1 * bc1;  r[7]  = b0 * bd0 + b1 * bd1;
        r[8]  = c0 * ba0 + c1 * ba1;  r[9]  = c0 * bb0 + c1 * bb1;
        r[10] = c0 * bc0 + c1 * bc1;  r[11] = c0 * bd0 + c1 * bd1;
        r[12] = d0 * ba0 + d1 * ba1;  r[13] = d0 * bb0 + d1 * bb1;
        r[14] = d0 * bc0 + d1 * bc1;  r[15] = d0 * bd0 + d1 * bd1;
        #pragma unroll
        for (int o = 16; o; o >>= 1)
            #pragma unroll
            for (int q = 0; q < 16; q++)
                r[q] += __shfl_xor_sync(0xffffffffu, r[q], o);
        if (lane == 0) {
            __half2* dd = (__half2*)(g_mmath + (size_t)rowi * 4);
            #pragma unroll
            for (int q = 0; q < 8; q++)
                dd[q] = __floats2half2_rn(r[q * 2], r[q * 2 + 1]);
        }
    }
}

// ---------------- fp16 GEMM constants (128x128, 256 thr, 3-stage) -----------
#define BM 128
#define BN 128
#define HBK 64
#define HLDS 72
#define HSTRIDE ((BM + BN) * HLDS)
#define GEMM_SMEM_H (3 * HSTRIDE * 2)               // 110592 B

typedef wmma::fragment<wmma::matrix_a, 16, 16, 16, __half, wmma::row_major> AFH;
typedef wmma::fragment<wmma::matrix_b, 16, 16, 16, __half, wmma::col_major> BFH;
typedef wmma::fragment<wmma::accumulator, 16, 16, 16, float> CFH;
typedef wmma::fragment<wmma::accumulator, 16, 16, 16, __half> CHH;

__device__ __forceinline__ void h_issue(const __half* A, const __half* B, __half* smh,
                                        int t, int m0, int n0, int K, int Nvalid,
                                        int kt, int s)
{
    int k0 = kt * HBK;
    __half* dstA0 = smh + s * HSTRIDE;
    __half* dstB0 = dstA0 + BM * HLDS;
    #pragma unroll
    for (int i = 0; i < 4; i++) {
        int id = t + i * 256;
        int row = id >> 3, c8 = id & 7;
        const __half* gA = A + (size_t)(m0 + row) * K + k0 + c8 * 8;
        unsigned int da = (unsigned int)__cvta_generic_to_shared(dstA0 + row * HLDS + c8 * 8);
        asm volatile("cp.async.cg.shared.global [%0], [%1], 16;\n" :: "r"(da), "l"(gA));
        int brow = n0 + row;
        const __half* gB = B + (size_t)brow * K + k0 + c8 * 8;
        unsigned int db = (unsigned int)__cvta_generic_to_shared(dstB0 + row * HLDS + c8 * 8);
        int sz = (brow < Nvalid) ? 16 : 0;
        asm volatile("cp.async.cg.shared.global [%0], [%1], 16, %2;\n" :: "r"(db), "l"(gB), "r"(sz));
    }
    asm volatile("cp.async.commit_group;\n" ::: "memory");
}

// ================= FUSED: GEMM1 mainloop + middle epilogue ===================
// epilogue smem layout (halves, overlaying the pipeline region):
//   hStage 256*72 | hIn 128*72 | hB 128*72 | hV,hS,hQ 64*72 each | floats: sKb 256, sqb 64, smw 64, sbias 128
constexpr int EP_STAGE = 0;
constexpr int EP_IN    = 256 * 72;
constexpr int EP_B     = EP_IN + 128 * 72;
constexpr int EP_V     = EP_B + 128 * 72;
constexpr int EP_S     = EP_V + 64 * 72;
constexpr int EP_Q     = EP_S + 64 * 72;
constexpr int EP_F     = EP_Q + 64 * 72;     // float region starts here (half idx, even)

__global__ __launch_bounds__(256, 2) void gemm1_fused(
    const __half* __restrict__ A, const __half* __restrict__ B,
    const float* __restrict__ V_slow, const float* __restrict__ sem_mem,
    const float* __restrict__ mix_w, const float* __restrict__ mix_b,
    const float* __restrict__ q_w, const float* __restrict__ q_b)
{
    extern __shared__ __half smh[];
    int t = threadIdx.x;
    int m0 = blockIdx.y * BM, n0 = blockIdx.x * BN;
    int w = t >> 5, wm = w & 1, wn = w >> 1;
    const int KT = FF / HBK;   // 8

    CFH acc[4][2];
    #pragma unroll
    for (int i = 0; i < 4; i++)
        #pragma unroll
        for (int j = 0; j < 2; j++) wmma::fill_fragment(acc[i][j], 0.0f);

    h_issue(A, B, smh, t, m0, n0, FF, HH, 0, 0);
    h_issue(A, B, smh, t, m0, n0, FF, HH, 1, 1);

    for (int kt = 0; kt < KT; kt++) {
        if (kt == KT - 1) asm volatile("cp.async.wait_group 0;\n" ::: "memory");
        else              asm volatile("cp.async.wait_group 1;\n" ::: "memory");
        __syncthreads();
        if (kt + 2 < KT)
            h_issue(A, B, smh, t, m0, n0, FF, HH, kt + 2, (kt + 2) % 3);

        const __half* sa = smh + (kt % 3) * HSTRIDE;
        const __half* sb = sa + BM * HLDS;
        #pragma unroll
        for (int kk = 0; kk < HBK / 16; kk++) {
            AFH af[4]; BFH bf[2];
            #pragma unroll
            for (int i = 0; i < 4; i++)
                wmma::load_matrix_sync(af[i], sa + (wm * 64 + i * 16) * HLDS + kk * 16, HLDS);
            #pragma unroll
            for (int j = 0; j < 2; j++)
                wmma::load_matrix_sync(bf[j], sb + (wn * 32 + j * 16) * HLDS + kk * 16, HLDS);
            #pragma unroll
            for (int i = 0; i < 4; i++)
                #pragma unroll
                for (int j = 0; j < 2; j++)
                    wmma::mma_sync(acc[i][j], af[i], bf[j], acc[i][j]);
        }
    }
    __syncthreads();   // pipeline smem dead; epilogue regions take over

    // ---- epilogue buffers ----
    __half* hStage = smh + EP_STAGE;
    __half* hIn    = smh + EP_IN;
    __half* hB     = smh + EP_B;
    __half* hV     = smh + EP_V;
    __half* hS     = smh + EP_S;
    __half* hQ     = smh + EP_Q;
    float*  sKb    = (float*)(smh + EP_F);   // 256
    float*  sqb    = sKb + 256;              // 64
    float*  smw    = sqb + 64;               // 64
    float*  sbias  = smw + 64;               // 128

    // stage accs as fp16: hStage[(node*128 + batchrow)*72 + dcol]
    #pragma unroll
    for (int i = 0; i < 4; i++)
        #pragma unroll
        for (int j = 0; j < 2; j++) {
            int col = wn * 32 + j * 16;
            int node = col >> 6, dcol = col & 63;
            CHH h;
            #pragma unroll
            for (int e = 0; e < h.num_elements; e++)
                h.x[e] = __float2half_rn(acc[i][j].x[e]);
            wmma::store_matrix_sync(&hStage[(node * 128 + wm * 64 + i * 16) * 72 + dcol], h, 72,
                                    wmma::mem_row_major);
        }

    // weights (L2-resident) — loaded concurrently with staging
    for (int i = t; i < DD * DD; i += 256) {
        int r = i >> 6, c2 = i & 63;
        hV[r * 72 + c2] = __float2half_rn(V_slow[i]);
        hS[r * 72 + c2] = __float2half_rn(sem_mem[i]);
        hQ[r * 72 + c2] = __float2half_rn(q_w[i]);
    }
    sKb[t] = g_K[t];
    if (t < 64) { sqb[t] = q_b[t]; smw[t] = mix_w[t]; }
    if (t < 128) sbias[t] = g_bin2[n0 + t];
    float mixb = mix_b[0];

    int rb = (w >> 1) * 32;             // 4 row-blocks of 32 (128 rows)
    int cb = (w & 1) * 32;              // 2 col-blocks of 32
    int n2 = t >> 1, dh = (t & 1) * 32;

    for (int hh = 0; hh < 2; hh++) {
        __syncthreads();

        // phase1: hIn = fp16(agg(h) + bias)
        {
            const __half2* src = (const __half2*)&hStage[(hh * 128 + n2) * 72 + dh];
            __half2* dst = (__half2*)&hIn[n2 * 72 + dh];
            const float* bp = &sbias[hh * 64 + dh];
            #pragma unroll
            for (int d = 0; d < 16; d++) {
                float2 f = __half22float2(src[d]);
                dst[d] = __floats2half2_rn(f.x + bp[d * 2], f.y + bp[d * 2 + 1]);
            }
        }
        __syncthreads();

        // matmul1: v = clip(agg @ V^T), y = clip(agg @ S^T)
        CHH hv[2][2], hy[2][2];
        {
            CFH vf[2][2], yf[2][2];
            #pragma unroll
            for (int i = 0; i < 2; i++)
                #pragma unroll
                for (int j = 0; j < 2; j++) { wmma::fill_fragment(vf[i][j], 0.f); wmma::fill_fragment(yf[i][j], 0.f); }
            #pragma unroll
            for (int kk = 0; kk < 4; kk++) {
                AFH a0, a1; BFH bv0, bv1, bs0, bs1;
                wmma::load_matrix_sync(a0, &hIn[(rb     ) * 72 + kk * 16], 72);
                wmma::load_matrix_sync(a1, &hIn[(rb + 16) * 72 + kk * 16], 72);
                wmma::load_matrix_sync(bv0, &hV[(cb     ) * 72 + kk * 16], 72);
                wmma::load_matrix_sync(bv1, &hV[(cb + 16) * 72 + kk * 16], 72);
                wmma::load_matrix_sync(bs0, &hS[(cb     ) * 72 + kk * 16], 72);
                wmma::load_matrix_sync(bs1, &hS[(cb + 16) * 72 + kk * 16], 72);
                wmma::mma_sync(vf[0][0], a0, bv0, vf[0][0]);
                wmma::mma_sync(vf[0][1], a0, bv1, vf[0][1]);
                wmma::mma_sync(vf[1][0], a1, bv0, vf[1][0]);
                wmma::mma_sync(vf[1][1], a1, bv1, vf[1][1]);
                wmma::mma_sync(yf[0][0], a0, bs0, yf[0][0]);
                wmma::mma_sync(yf[0][1], a0, bs1, yf[0][1]);
                wmma::mma_sync(yf[1][0], a1, bs0, yf[1][0]);
                wmma::mma_sync(yf[1][1], a1, bs1, yf[1][1]);
            }
            #pragma unroll
            for (int i = 0; i < 2; i++)
                #pragma unroll
                for (int j = 0; j < 2; j++)
                    #pragma unroll
                    for (int e = 0; e < 8; e++) {
                        hv[i][j].x[e] = __float2half_rn(clip3(vf[i][j].x[e]));
                        hy[i][j].x[e] = __float2half_rn(clip3(yf[i][j].x[e]));
                    }
        }
        __syncthreads();
        #pragma unroll
        for (int i = 0; i < 2; i++)
            #pragma unroll
            for (int j = 0; j < 2; j++) {
                wmma::store_matrix_sync(&hIn[(rb + i * 16) * 72 + cb + j * 16], hy[i][j], 72, wmma::mem_row_major);
                wmma::store_matrix_sync(&hB[(rb + i * 16) * 72 + cb + j * 16], hv[i][j], 72, wmma::mem_row_major);
            }
        __syncthreads();

        // mix = sigmoid(v . mix_w + mix_b)
        float m;
        {
            const __half2* vp2 = (const __half2*)&hB[n2 * 72 + dh];
            float acc2 = 0.f;
            #pragma unroll
            for (int d = 0; d < 16; d++) {
                float2 f = __half22float2(vp2[d]);
                acc2 += f.x * smw[dh + d * 2] + f.y * smw[dh + d * 2 + 1];
            }
            acc2 += __shfl_xor_sync(0xffffffffu, acc2, 1);
            m = sigmoidf_(acc2 + mixb);
        }

        // matmul2: vp = clip(y @ V^T) -> hIn
        {
            CFH pf[2][2];
            #pragma unroll
            for (int i = 0; i < 2; i++)
                #pragma unroll
                for (int j = 0; j < 2; j++) wmma::fill_fragment(pf[i][j], 0.f);
            #pragma unroll
            for (int kk = 0; kk < 4; kk++) {
                AFH a0, a1; BFH bv0, bv1;
                wmma::load_matrix_sync(a0, &hIn[(rb     ) * 72 + kk * 16], 72);
                wmma::load_matrix_sync(a1, &hIn[(rb + 16) * 72 + kk * 16], 72);
                wmma::load_matrix_sync(bv0, &hV[(cb     ) * 72 + kk * 16], 72);
                wmma::load_matrix_sync(bv1, &hV[(cb + 16) * 72 + kk * 16], 72);
                wmma::mma_sync(pf[0][0], a0, bv0, pf[0][0]);
                wmma::mma_sync(pf[0][1], a0, bv1, pf[0][1]);
                wmma::mma_sync(pf[1][0], a1, bv0, pf[1][0]);
                wmma::mma_sync(pf[1][1], a1, bv1, pf[1][1]);
            }
            CHH hp[2][2];
            #pragma unroll
            for (int i = 0; i < 2; i++)
                #pragma unroll
                for (int j = 0; j < 2; j++)
                    #pragma unroll
                    for (int e = 0; e < 8; e++)
                        hp[i][j].x[e] = __float2half_rn(clip3(pf[i][j].x[e]));
            __syncthreads();
            #pragma unroll
            for (int i = 0; i < 2; i++)
                #pragma unroll
                for (int j = 0; j < 2; j++)
                    wmma::store_matrix_sync(&hIn[(rb + i * 16) * 72 + cb + j * 16], hp[i][j], 72, wmma::mem_row_major);
        }
        __syncthreads();

        // cell = fp16(clip(m*v + (1-m)*vp)) -> hIn
        {
            const __half2* vv = (const __half2*)&hB[n2 * 72 + dh];
            __half2* pp = (__half2*)&hIn[n2 * 72 + dh];
            #pragma unroll
            for (int d = 0; d < 16; d++) {
                float2 fv = __half22float2(vv[d]);
                float2 fp = __half22float2(pp[d]);
                pp[d] = __floats2half2_rn(clip3(m * fv.x + (1.f - m) * fp.x),
                                          clip3(m * fv.y + (1.f - m) * fp.y));
            }
        }
        __syncthreads();

        // matmul3: Q = cell @ q_w^T -> hB
        {
            CFH qf[2][2];
            #pragma unroll
            for (int i = 0; i < 2; i++)
                #pragma unroll
                for (int j = 0; j < 2; j++) wmma::fill_fragment(qf[i][j], 0.f);
            #pragma unroll
            for (int kk = 0; kk < 4; kk++) {
                AFH a0, a1; BFH bq0, bq1;
                wmma::load_matrix_sync(a0, &hIn[(rb     ) * 72 + kk * 16], 72);
                wmma::load_matrix_sync(a1, &hIn[(rb + 16) * 72 + kk * 16], 72);
                wmma::load_matrix_sync(bq0, &hQ[(cb     ) * 72 + kk * 16], 72);
                wmma::load_matrix_sync(bq1, &hQ[(cb + 16) * 72 + kk * 16], 72);
                wmma::mma_sync(qf[0][0], a0, bq0, qf[0][0]);
                wmma::mma_sync(qf[0][1], a0, bq1, qf[0][1]);
                wmma::mma_sync(qf[1][0], a1, bq0, qf[1][0]);
                wmma::mma_sync(qf[1][1], a1, bq1, qf[1][1]);
            }
            CHH hq[2][2];
            #pragma unroll
            for (int i = 0; i < 2; i++)
                #pragma unroll
                for (int j = 0; j < 2; j++) {
                    #pragma unroll
                    for (int e = 0; e < 8; e++)
                        hq[i][j].x[e] = __float2half_rn(qf[i][j].x[e]);
                    wmma::store_matrix_sync(&hB[(rb + i * 16) * 72 + cb + j * 16], hq[i][j], 72, wmma::mem_row_major);
                }
        }
        __syncthreads();

        // attention: softmax -> g_wh  (batch m0+n2, node bx*2+hh)
        {
            const __half2* qp = (const __half2*)&hB[n2 * 72 + dh];
            float qv[32];
            #pragma unroll
            for (int d = 0; d < 16; d++) {
                float2 f = __half22float2(qp[d]);
                qv[d * 2]     = f.x + sqb[dh + d * 2];
                qv[d * 2 + 1] = f.y + sqb[dh + d * 2 + 1];
            }
            float s0 = 0.f, s1 = 0.f, s2 = 0.f, s3 = 0.f;
            #pragma unroll
            for (int d = 0; d < 32; d++) {
                s0 += qv[d] * sKb[dh + d];
                s1 += qv[d] * sKb[64 + dh + d];
                s2 += qv[d] * sKb[128 + dh + d];
                s3 += qv[d] * sKb[192 + dh + d];
            }
            s0 += __shfl_xor_sync(0xffffffffu, s0, 1);
            s1 += __shfl_xor_sync(0xffffffffu, s1, 1);
            s2 += __shfl_xor_sync(0xffffffffu, s2, 1);
            s3 += __shfl_xor_sync(0xffffffffu, s3, 1);
            if ((t & 1) == 0) {
                s0 *= 0.125f; s1 *= 0.125f; s2 *= 0.125f; s3 *= 0.125f;
                float mx = fmaxf(fmaxf(s0, s1), fmaxf(s2, s3));
                float e0 = expf(s0 - mx), e1 = expf(s1 - mx), e2 = expf(s2 - mx), e3 = expf(s3 - mx);
                float inv = 1.f / (e0 + e1 + e2 + e3);
                int nb = blockIdx.x * 2 + hh;
                __half2* dst = (__half2*)(g_wh + ((size_t)(m0 + n2) * NN + nb) * 4);
                dst[0] = __floats2half2_rn(e0 * inv, e1 * inv);
                dst[1] = __floats2half2_rn(e2 * inv, e3 * inv);
            }
        }
    }
}

// ---------------- readout GEMM (fp16 MMA, fused bias, direct to d_out) -------
__global__ __launch_bounds__(256, 2) void gemm_readout(
    const __half* __restrict__ A, const __half* __restrict__ B, float* __restrict__ C,
    int Nvalid, int K, int ldc, const float* __restrict__ bias)
{
    extern __shared__ __half smh[];
    float* smf = (float*)smh;
    int t = threadIdx.x;
    int m0 = blockIdx.y * BM, n0 = blockIdx.x * BN;
    int w = t >> 5, wm = w & 1, wn = w >> 1;
    int KT = K / HBK;

    CFH acc[4][2];
    #pragma unroll
    for (int i = 0; i < 4; i++)
        #pragma unroll
        for (int j = 0; j < 2; j++) wmma::fill_fragment(acc[i][j], 0.0f);

    h_issue(A, B, smh, t, m0, n0, K, Nvalid, 0, 0);
    h_issue(A, B, smh, t, m0, n0, K, Nvalid, 1, 1);

    for (int kt = 0; kt < KT; kt++) {
        if (kt == KT - 1) asm volatile("cp.async.wait_group 0;\n" ::: "memory");
        else              asm volatile("cp.async.wait_group 1;\n" ::: "memory");
        __syncthreads();
        if (kt + 2 < KT)
            h_issue(A, B, smh, t, m0, n0, K, Nvalid, kt + 2, (kt + 2) % 3);

        const __half* sa = smh + (kt % 3) * HSTRIDE;
        const __half* sb = sa + BM * HLDS;
        #pragma unroll
        for (int kk = 0; kk < HBK / 16; kk++) {
            AFH af[4]; BFH bf[2];
            #pragma unroll
            for (int i = 0; i < 4; i++)
                wmma::load_matrix_sync(af[i], sa + (wm * 64 + i * 16) * HLDS + kk * 16, HLDS);
            #pragma unroll
            for (int j = 0; j < 2; j++)
                wmma::load_matrix_sync(bf[j], sb + (wn * 32 + j * 16) * HLDS + kk * 16, HLDS);
            #pragma unroll
            for (int i = 0; i < 4; i++)
                #pragma unroll
                for (int j = 0; j < 2; j++)
                    wmma::mma_sync(acc[i][j], af[i], bf[j], acc[i][j]);
        }
    }

    __syncthreads();
    float* tile = smf;
    #pragma unroll
    for (int i = 0; i < 4; i++)
        #pragma unroll
        for (int j = 0; j < 2; j++)
            wmma::store_matrix_sync(tile + (wm * 64 + i * 16) * 132 + wn * 32 + j * 16,
                                    acc[i][j], 132, wmma::mem_row_major);
    __syncthreads();
    for (int idx = t; idx < BM * BN; idx += 256) {
        int r = idx >> 7, c = idx & 127;
        int col = n0 + c;
        if (col < Nvalid)
            C[(size_t)(m0 + r) * ldc + col] = tile[r * 132 + c] + bias[col];
    }
}

// ---------------- launcher ---------------------------------------------------
extern "C" void kernel_launch(void* const* d_in, const int* in_sizes, int n_in,
                              void* d_out, int out_size)
{
    (void)in_sizes; (void)n_in; (void)out_size;
    const float* x      = (const float*)d_in[0];
    const float* W_in   = (const float*)d_in[1];
    const float* b_in   = (const float*)d_in[2];
    const float* adj_w  = (const float*)d_in[3];
    const float* V_slow = (const float*)d_in[5];
    const float* sem    = (const float*)d_in[6];
    const float* mix_w  = (const float*)d_in[7];
    const float* mix_b  = (const float*)d_in[8];
    const float* basis  = (const float*)d_in[9];
    const float* q_w    = (const float*)d_in[10];
    const float* q_b    = (const float*)d_in[11];
    const float* k_w    = (const float*)d_in[12];
    const float* k_b    = (const float*)d_in[13];
    const float* W_out  = (const float*)d_in[14];
    const float* b_out  = (const float*)d_in[15];
    float* out = (float*)d_out;

    cudaFuncSetAttribute(gemm1_fused,  cudaFuncAttributeMaxDynamicSharedMemorySize, GEMM_SMEM_H);
    cudaFuncSetAttribute(gemm_readout, cudaFuncAttributeMaxDynamicSharedMemorySize, GEMM_SMEM_H);

    void *p_wh = 0, *p_mmath = 0, *p_win2h = 0, *p_xh = 0;
    cudaGetSymbolAddress(&p_wh,     g_wh);
    cudaGetSymbolAddress(&p_mmath,  g_mmath);
    cudaGetSymbolAddress(&p_win2h,  g_win2h);
    cudaGetSymbolAddress(&p_xh,     g_xh);

    prep_kernel<<<1, 256>>>(adj_w, k_w, k_b, basis);
    prep2_kernel<<<PREP2_GRID, 256>>>(W_in, b_in, x, W_out, basis);

    // fused: agg GEMM + entire middle; emits softmax weights g_wh
    gemm1_fused<<<dim3(HH / BN, BB / BM), 256, GEMM_SMEM_H>>>(
        (const __half*)p_xh, (const __half*)p_win2h,
        V_slow, sem, mix_w, mix_b, q_w, q_b);

    // logits = wh @ Mmat^T + b_out  (fp16 MMA, direct store to d_out)
    gemm_readout<<<dim3(CPAD / BN, BB / BM), 256, GEMM_SMEM_H>>>(
        (const __half*)p_wh, (const __half*)p_mmath, out, CC, CPAD, CC, b_out);
}